// round 1
// baseline (speedup 1.0000x reference)
#include <cuda_runtime.h>

#define D 512
#define EPS 1e-9f

// Accumulators: [0]=sum_e, [1]=sum_e2, [2]=sum_t, [3]=sum_t2, [4]=sum_et
__device__ float g_acc[5 * D];

__global__ void zero_acc_kernel() {
    int i = blockIdx.x * blockDim.x + threadIdx.x;
    if (i < 5 * D) g_acc[i] = 0.0f;
}

__global__ void stats_kernel(const float* __restrict__ e,
                             const float* __restrict__ t,
                             int rows_per_block) {
    const int col = threadIdx.x;                 // 512 threads = 512 columns
    const long long r0 = (long long)blockIdx.x * rows_per_block;

    float se = 0.f, se2 = 0.f, st = 0.f, st2 = 0.f, set = 0.f;

    const float* ep = e + r0 * D + col;
    const float* tp = t + r0 * D + col;

    #pragma unroll 4
    for (int r = 0; r < rows_per_block; ++r) {
        float ev = ep[(long long)r * D];
        float tv = tp[(long long)r * D];
        se  += ev;
        se2 += ev * ev;
        st  += tv;
        st2 += tv * tv;
        set += ev * tv;
    }

    atomicAdd(&g_acc[0 * D + col], se);
    atomicAdd(&g_acc[1 * D + col], se2);
    atomicAdd(&g_acc[2 * D + col], st);
    atomicAdd(&g_acc[3 * D + col], st2);
    atomicAdd(&g_acc[4 * D + col], set);
}

__global__ void finalize_kernel(float* __restrict__ out, float B) {
    const int col = threadIdx.x;   // 512 threads, 1 block
    __shared__ float red[512];

    float se  = g_acc[0 * D + col];
    float se2 = g_acc[1 * D + col];
    float st  = g_acc[2 * D + col];
    float st2 = g_acc[3 * D + col];
    float set = g_acc[4 * D + col];

    float me = se / B;
    float mt = st / B;
    // unbiased variance (ddof=1)
    float var_e = (se2 - B * me * me) / (B - 1.0f);
    float var_t = (st2 - B * mt * mt) / (B - 1.0f);
    float sd_e = sqrtf(fmaxf(var_e, 0.0f)) + EPS;
    float sd_t = sqrtf(fmaxf(var_t, 0.0f)) + EPS;

    // sum_b (e-me)(t-mt) = set - B*me*mt
    float cov = set - B * me * mt;
    float c = cov / (sd_e * sd_t) / B;
    float d = 1.0f - c;
    float partial = d * d;

    red[col] = partial;
    __syncthreads();
    #pragma unroll
    for (int s = 256; s > 0; s >>= 1) {
        if (col < s) red[col] += red[col + s];
        __syncthreads();
    }
    if (col == 0) out[0] = red[0];
}

extern "C" void kernel_launch(void* const* d_in, const int* in_sizes, int n_in,
                              void* d_out, int out_size) {
    const float* e = (const float*)d_in[0];
    const float* t = (const float*)d_in[1];
    float* out = (float*)d_out;

    const long long total = in_sizes[0];
    const int B = (int)(total / D);          // 65536

    const int nblocks = 512;                 // 128 rows per block
    const int rows_per_block = B / nblocks;

    zero_acc_kernel<<<(5 * D + 511) / 512, 512>>>();
    stats_kernel<<<nblocks, D>>>(e, t, rows_per_block);
    finalize_kernel<<<1, D>>>(out, (float)B);
}